// round 16
// baseline (speedup 1.0000x reference)
#include <cuda_runtime.h>
#include <cuda_bf16.h>
#include <cstdint>
#include <cstdio>

// Problem sizes (reference setup_inputs: N=50000, E=800000, D=128, H=4)
#define NMAX   50000
#define EMAX   800000
#define TOTMAX (EMAX + NMAX)   // edges + self loops

// ---------------- scratch (device globals; no allocation allowed) ----------------
// packed bf16x2 hi/lo operands (word w holds k = 2w, 2w+1)
__device__ __align__(16) uint32_t g_aggH[(size_t)NMAX * 256];  // layer1 aggregated x (hi)
__device__ __align__(16) uint32_t g_aggL[(size_t)NMAX * 256];  // (lo)
__device__ __align__(16) uint32_t g_h1H [(size_t)NMAX * 256];  // relu(agg@W1+b1) (hi)
__device__ __align__(16) uint32_t g_h1L [(size_t)NMAX * 256];  // (lo)
__device__ __align__(16) uint32_t g_w1H [64 * 512];            // W1 packed [pk][n]
__device__ __align__(16) uint32_t g_w1L [64 * 512];
__device__ __align__(16) uint32_t g_w2H [256 * 128];           // W2 packed [pk][n]
__device__ __align__(16) uint32_t g_w2L [256 * 128];
__device__ __align__(16) float g_h2pre[(size_t)NMAX * 128];    // h1 @ W2  [N,128]
__device__ __align__(16) float g_es   [NMAX * 4];
__device__ __align__(16) float g_ed   [NMAX * 4];
__device__ __align__(16) float g_ebuf [(size_t)TOTMAX * 4];    // per-edge exp weights
__device__ __align__(16) float g_ws   [4 * 128];               // W1_h @ a1_src[h]
__device__ __align__(16) float g_wd   [4 * 128];               // W1_h @ a1_dst[h]
__device__ int   g_cnt  [NMAX];
__device__ int   g_off  [NMAX + 1];
__device__ int   g_cur  [NMAX];
__device__ int   g_srcs [TOTMAX];               // CSR: src node per edge slot

// ---------------- bf16 hi/lo pack helpers ----------------
__device__ __forceinline__ uint32_t pack2bf(float a, float b) {
    __nv_bfloat162 t = __floats2bfloat162_rn(a, b);   // .x = a (low half)
    return *reinterpret_cast<uint32_t*>(&t);
}
__device__ __forceinline__ void packHL(float x, float y, uint32_t& H, uint32_t& L) {
    __nv_bfloat16 hx = __float2bfloat16_rn(x);
    __nv_bfloat16 hy = __float2bfloat16_rn(y);
    H = pack2bf(__bfloat162float(hx), __bfloat162float(hy));
    L = pack2bf(x - __bfloat162float(hx), y - __bfloat162float(hy));
}

// ---------------- prep: pack W1/W2 + init cnt ----------------
__global__ void k_prep(const float* __restrict__ W1, const float* __restrict__ W2, int n) {
    int i = blockIdx.x * blockDim.x + threadIdx.x;
    if (i < 32768) {                       // W1: [128][512] -> [64][512] packed
        int pk = i >> 9, nn = i & 511;
        packHL(W1[(2 * pk) * 512 + nn], W1[(2 * pk + 1) * 512 + nn], g_w1H[i], g_w1L[i]);
    } else if (i < 65536) {                // W2: [512][128] -> [256][128] packed
        int j = i - 32768;
        int pk = j >> 7, nn = j & 127;
        packHL(W2[(2 * pk) * 128 + nn], W2[(2 * pk + 1) * 128 + nn], g_w2H[j], g_w2L[j]);
    } else if (i < 65536 + n) {
        g_cnt[i - 65536] = 1;              // 1 = the self loop
    }
}

__global__ void k_hist(const int* __restrict__ dst, int E) {
    int i = blockIdx.x * blockDim.x + threadIdx.x;
    if (i < E) atomicAdd(&g_cnt[dst[i]], 1);
}

// single-block hierarchical exclusive scan
__global__ void k_scan(int n) {
    __shared__ int wsum[32];
    __shared__ int s_total;
    const int t    = threadIdx.x;
    const int lane = t & 31;
    const int w    = t >> 5;
    const int per  = (n + blockDim.x - 1) / blockDim.x;
    const int start = t * per;
    const int end   = min(start + per, n);

    int sum = 0;
    for (int i = start; i < end; i++) sum += g_cnt[i];

    int inc = sum;
    #pragma unroll
    for (int o = 1; o < 32; o <<= 1) {
        int v = __shfl_up_sync(0xffffffffu, inc, o);
        if (lane >= o) inc += v;
    }
    if (lane == 31) wsum[w] = inc;
    __syncthreads();
    if (w == 0) {
        int v = wsum[lane];
        int winc = v;
        #pragma unroll
        for (int o = 1; o < 32; o <<= 1) {
            int u = __shfl_up_sync(0xffffffffu, winc, o);
            if (lane >= o) winc += u;
        }
        wsum[lane] = winc - v;
        if (lane == 31) s_total = winc;
    }
    __syncthreads();

    int run = (inc - sum) + wsum[w];
    for (int i = start; i < end; i++) {
        int c = g_cnt[i];
        g_off[i] = run;
        g_cur[i] = run;
        run += c;
    }
    if (t == 0) g_off[n] = s_total;
}

__global__ void k_scatter(const int* __restrict__ src,
                          const int* __restrict__ dst, int E, int n) {
    int i = blockIdx.x * blockDim.x + threadIdx.x;
    if (i < E) {
        int d = dst[i];
        int p = atomicAdd(&g_cur[d], 1);
        g_srcs[p] = src[i];
    } else if (i < E + n) {
        int node = i - E;
        int p = atomicAdd(&g_cur[node], 1);
        g_srcs[p] = node;
    }
}

// ---------------- fold attention vectors through W1 ----------------
__global__ void k_prep_ws(const float* __restrict__ W1,
                          const float* __restrict__ a1s,
                          const float* __restrict__ a1d) {
    int t = threadIdx.x;          // 512 threads: h = t>>7, k = t&127
    int h = t >> 7, k = t & 127;
    float s = 0.f, d = 0.f;
    const float* wrow = W1 + (size_t)k * 512 + h * 128;
    const float* as   = a1s + h * 128;
    const float* ad   = a1d + h * 128;
    #pragma unroll 8
    for (int c = 0; c < 128; c++) {
        float wv = wrow[c];
        s += wv * as[c];
        d += wv * ad[c];
    }
    g_ws[t] = s;
    g_wd[t] = d;
}

// ---------------- layer-1 scores from x directly ----------------
__global__ void k_scores1(const float* __restrict__ x, int n) {
    int gt   = blockIdx.x * blockDim.x + threadIdx.x;
    int wid  = gt >> 5;
    int lane = gt & 31;
    if (wid >= n) return;
    float4 v = ((const float4*)x)[(size_t)wid * 32 + lane];
    float s[4], d[4];
    #pragma unroll
    for (int h = 0; h < 4; h++) {
        float4 w = ((const float4*)g_ws)[h * 32 + lane];
        float4 u = ((const float4*)g_wd)[h * 32 + lane];
        s[h] = v.x * w.x + v.y * w.y + v.z * w.z + v.w * w.w;
        d[h] = v.x * u.x + v.y * u.y + v.z * u.z + v.w * u.w;
    }
    #pragma unroll
    for (int o = 16; o; o >>= 1) {
        #pragma unroll
        for (int h = 0; h < 4; h++) {
            s[h] += __shfl_down_sync(0xffffffffu, s[h], o);
            d[h] += __shfl_down_sync(0xffffffffu, d[h], o);
        }
    }
    if (lane == 0) {
        #pragma unroll
        for (int h = 0; h < 4; h++) {
            g_es[wid * 4 + h] = s[h];
            g_ed[wid * 4 + h] = d[h];
        }
    }
}

// ---------------- layer-2 scores ----------------
__global__ void k_scores2(const float* __restrict__ hpre,
                          const float* __restrict__ a_src,
                          const float* __restrict__ a_dst, int n) {
    int gt   = blockIdx.x * blockDim.x + threadIdx.x;
    int wid  = gt >> 5;
    int lane = gt & 31;
    if (wid >= n) return;
    float4 v = ((const float4*)hpre)[(size_t)wid * 32 + lane];
    float4 a = ((const float4*)a_src)[lane];
    float4 b = ((const float4*)a_dst)[lane];
    float s = v.x * a.x + v.y * a.y + v.z * a.z + v.w * a.w;
    float d = v.x * b.x + v.y * b.y + v.z * b.z + v.w * b.w;
    #pragma unroll
    for (int o = 16; o; o >>= 1) {
        s += __shfl_down_sync(0xffffffffu, s, o);
        d += __shfl_down_sync(0xffffffffu, d, o);
    }
    if (lane == 0) { g_es[wid] = s; g_ed[wid] = d; }
}

// ---------------- fused edge pass, layer 1 (no-max softmax; z folded); packed agg out ----
__global__ void k_edge1(const float* __restrict__ x, int n) {
    int gt   = blockIdx.x * blockDim.x + threadIdx.x;
    int wid  = gt >> 5;
    int lane = gt & 31;
    if (wid >= n) return;
    const int node = wid;
    const int s0 = g_off[node], s1 = g_off[node + 1];

    // ---- phase 1: w = exp(leakyrelu(es+ed)); store only ----
    float edv[4];
    #pragma unroll
    for (int h = 0; h < 4; h++) edv[h] = g_ed[node * 4 + h];
    for (int j = s0 + lane; j < s1; j += 32) {
        int s = g_srcs[j];
        float4 ev = ((const float4*)g_es)[s];
        float e4[4] = {ev.x, ev.y, ev.z, ev.w};
        float o4[4];
        #pragma unroll
        for (int h = 0; h < 4; h++) {
            float e = e4[h] + edv[h];
            e = (e > 0.f) ? e : 0.2f * e;            // leaky_relu 0.2
            o4[h] = __expf(e);
        }
        ((float4*)g_ebuf)[j] = make_float4(o4[0], o4[1], o4[2], o4[3]);
    }
    __syncwarp();

    // ---- phase 2: aggregate raw x; z in-loop (weights are warp-uniform) ----
    const float4* x4  = (const float4*)x;
    const float4* al4 = (const float4*)g_ebuf;
    float z0 = 0.f, z1 = 0.f, z2 = 0.f, z3 = 0.f;
    float4 a0 = make_float4(0.f,0.f,0.f,0.f), a1 = a0, a2 = a0, a3 = a0;
    #pragma unroll 2
    for (int j = s0; j < s1; j++) {
        float4 al = al4[j];
        int s = g_srcs[j];
        float4 v = x4[(size_t)s * 32 + lane];
        z0 += al.x; z1 += al.y; z2 += al.z; z3 += al.w;
        a0.x += al.x * v.x; a0.y += al.x * v.y; a0.z += al.x * v.z; a0.w += al.x * v.w;
        a1.x += al.y * v.x; a1.y += al.y * v.y; a1.z += al.y * v.z; a1.w += al.y * v.w;
        a2.x += al.z * v.x; a2.y += al.z * v.y; a2.z += al.z * v.z; a2.w += al.z * v.w;
        a3.x += al.w * v.x; a3.y += al.w * v.y; a3.z += al.w * v.z; a3.w += al.w * v.w;
    }
    float zi0 = 1.0f / z0, zi1 = 1.0f / z1, zi2 = 1.0f / z2, zi3 = 1.0f / z3;
    a0.x *= zi0; a0.y *= zi0; a0.z *= zi0; a0.w *= zi0;
    a1.x *= zi1; a1.y *= zi1; a1.z *= zi1; a1.w *= zi1;
    a2.x *= zi2; a2.y *= zi2; a2.z *= zi2; a2.w *= zi2;
    a3.x *= zi3; a3.y *= zi3; a3.z *= zi3; a3.w *= zi3;
    // write packed hi/lo: lane owns k = 4*lane..4*lane+3 -> words 2*lane, 2*lane+1
    uint2* aggH2 = (uint2*)g_aggH;
    uint2* aggL2 = (uint2*)g_aggL;
    size_t base = (size_t)node * 128 + lane;   // uint2 index: node*128 + h*32 + lane
    float4 av[4] = {a0, a1, a2, a3};
    #pragma unroll
    for (int h = 0; h < 4; h++) {
        uint32_t H0, L0, H1, L1;
        packHL(av[h].x, av[h].y, H0, L0);
        packHL(av[h].z, av[h].w, H1, L1);
        aggH2[base + h * 32] = make_uint2(H0, H1);
        aggL2[base + h * 32] = make_uint2(L0, L1);
    }
}

// ---------------- fused edge pass, layer 2 (no-max softmax; z folded) + FC ----------------
__global__ void k_edge2(const float* __restrict__ b2, const float* __restrict__ fcw,
                        const float* __restrict__ fcb, float* __restrict__ out, int n) {
    int gt   = blockIdx.x * blockDim.x + threadIdx.x;
    int wid  = gt >> 5;
    int lane = gt & 31;
    if (wid >= n) return;
    const int node = wid;
    const int s0 = g_off[node], s1 = g_off[node + 1];

    float edv = g_ed[node];
    for (int j = s0 + lane; j < s1; j += 32) {
        int s = g_srcs[j];
        float e = g_es[s] + edv;
        e = (e > 0.f) ? e : 0.2f * e;
        g_ebuf[j] = __expf(e);
    }
    __syncwarp();

    const float4* hp4 = (const float4*)g_h2pre;
    float z = 0.f;
    float4 acc = make_float4(0.f, 0.f, 0.f, 0.f);
    #pragma unroll 2
    for (int j = s0; j < s1; j++) {
        float w = g_ebuf[j];
        int s = g_srcs[j];
        float4 v = hp4[(size_t)s * 32 + lane];
        z += w;
        acc.x += w * v.x;
        acc.y += w * v.y;
        acc.z += w * v.z;
        acc.w += w * v.w;
    }
    float zinv = 1.0f / z;
    acc.x *= zinv; acc.y *= zinv; acc.z *= zinv; acc.w *= zinv;
    float4 bv = ((const float4*)b2)[lane];
    float4 wv = ((const float4*)fcw)[lane];
    float s = (acc.x + bv.x) * wv.x + (acc.y + bv.y) * wv.y +
              (acc.z + bv.z) * wv.z + (acc.w + bv.w) * wv.w;
    #pragma unroll
    for (int o = 16; o; o >>= 1) s += __shfl_down_sync(0xffffffffu, s, o);
    if (lane == 0) out[node] = s + fcb[0];
}

// ---------------- bf16-split tensor-core GEMM (pre-packed operands; R15 structure) ------
#define MMA_BF16(d, a, b)                                                     \
    asm volatile("mma.sync.aligned.m16n8k16.row.col.f32.bf16.bf16.f32 "       \
                 "{%0,%1,%2,%3}, {%4,%5,%6,%7}, {%8,%9}, {%0,%1,%2,%3};"      \
                 : "+f"(d[0]), "+f"(d[1]), "+f"(d[2]), "+f"(d[3])             \
                 : "r"(a[0]), "r"(a[1]), "r"(a[2]), "r"(a[3]),                \
                   "r"(b[0]), "r"(b[1]))

// PACK: epilogue does bias+relu and writes packed bf16 hi/lo (CH/CL); else fp32 C.
template <bool PACK>
__global__ __launch_bounds__(256)
void mma_gemm(int M, int nT,
              const uint32_t* __restrict__ AH, const uint32_t* __restrict__ AL,
              int ldaw, int offAw,
              const uint32_t* __restrict__ BH, const uint32_t* __restrict__ BL,
              int ldn, int offBn,
              float* __restrict__ C, uint32_t* __restrict__ CH, uint32_t* __restrict__ CL,
              int ldc, int offC, const float* __restrict__ bias) {
    __shared__ uint32_t AsH[2][8][136], AsL[2][8][136];
    __shared__ uint32_t BsH[2][8][136], BsL[2][8][136];
    const int tid  = threadIdx.x;
    const int lane = tid & 31;
    const int wid  = tid >> 5;
    const int wm   = (wid & 3) * 32;   // 4 warps along m
    const int wn   = (wid >> 2) * 64;  // 2 warps along n
    const int mBase = blockIdx.y * 128;
    const int zAw = blockIdx.z * offAw;
    const int zBn = blockIdx.z * offBn;
    const int zC  = blockIdx.z * offC;

    const int aRow = tid >> 2;          // 0..63
    const int aPk  = (tid & 3) * 2;     // packed col base 0,2,4,6
    const int bPk  = tid >> 5;          // packed k row 0..7
    const int bN   = (tid & 31) * 4;    // 0..124

    float acc[2][8][4];
    #pragma unroll
    for (int i = 0; i < 2; i++)
        #pragma unroll
        for (int j = 0; j < 8; j++)
            #pragma unroll
            for (int q = 0; q < 4; q++) acc[i][j][q] = 0.f;

    // staging registers for the next tile (pre-packed: plain copies)
    uint2 ahr[2], alr[2];
    uint4 bhr, blr;

    // ---- ldg tile 0 ----
    {
        #pragma unroll
        for (int rr = 0; rr < 2; rr++) {
            int gr = mBase + aRow + rr * 64;
            if (gr < M) {
                const uint32_t* ap = AH + (size_t)gr * ldaw + zAw + aPk;
                const uint32_t* lp = AL + (size_t)gr * ldaw + zAw + aPk;
                ahr[rr] = *(const uint2*)ap;
                alr[rr] = *(const uint2*)lp;
            } else {
                ahr[rr] = make_uint2(0u, 0u);
                alr[rr] = make_uint2(0u, 0u);
            }
        }
        const uint32_t* bp = BH + (size_t)bPk * ldn + zBn + bN;
        const uint32_t* lp = BL + (size_t)bPk * ldn + zBn + bN;
        bhr = *(const uint4*)bp;
        blr = *(const uint4*)lp;
    }

    for (int t = 0; t < nT; t++) {
        const int cur = t & 1;
        // ---- sts staged regs into smem buf cur (same addressing as R15) ----
        #pragma unroll
        for (int rr = 0; rr < 2; rr++) {
            int mm = aRow + rr * 64;
            AsH[cur][aPk + 0][mm] = ahr[rr].x;
            AsH[cur][aPk + 1][mm] = ahr[rr].y;
            AsL[cur][aPk + 0][mm] = alr[rr].x;
            AsL[cur][aPk + 1][mm] = alr[rr].y;
        }
        *(uint4*)&BsH[cur][bPk][bN] = bhr;
        *(uint4*)&BsL[cur][bPk][bN] = blr;
        __syncthreads();

        // ---- issue ldg for tile t+1 ----
        if (t + 1 < nT) {
            int k0w = (t + 1) * 8;
            #pragma unroll
            for (int rr = 0; rr < 2; rr++) {
                int gr = mBase + aRow + rr * 64;
                if (gr < M) {
                    const uint32_t* ap = AH + (size_t)gr * ldaw + zAw + k0w + aPk;
                    const uint32_t* lp = AL + (size_t)gr * ldaw + zAw + k0w + aPk;
                    ahr[rr] = *(const uint2*)ap;
                    alr[rr] = *(const uint2*)lp;
                } else {
                    ahr[rr] = make_uint2(0u, 0u);
                    alr[rr] = make_uint2(0u, 0u);
                }
            }
            const uint32_t* bp = BH + (size_t)(k0w + bPk) * ldn + zBn + bN;
            const uint32_t* lp = BL + (size_t)(k0w + bPk) * ldn + zBn + bN;
            bhr = *(const uint4*)bp;
            blr = *(const uint4*)lp;
        }

        // ---- mma on buf cur (identical to R15) ----
        uint32_t ah[2][4], al[2][4];
        const int ar = wm + (lane >> 2);
        const int ac = lane & 3;
        #pragma unroll
        for (int i = 0; i < 2; i++) {
            int r = ar + i * 16;
            ah[i][0] = AsH[cur][ac][r];
            ah[i][1] = AsH[cur][ac][r + 8];
            ah[i][2] = AsH[cur][ac + 4][r];
            ah[i][3] = AsH[cur][ac + 4][r + 8];
            al[i][0] = AsL[cur][ac][r];
            al[i][1] = AsL[cur][ac][r + 8];
            al[i][2] = AsL[cur][ac + 4][r];
            al[i][3] = AsL[cur][ac + 4][r + 8];
        }
        #pragma unroll
        for (int jh = 0; jh < 2; jh++) {
            uint32_t bh[4][2], bl[4][2];
            const int rB = lane & 3;
            #pragma unroll
            for (int j = 0; j < 4; j++) {
                int c = wn + jh * 32 + j * 8 + (lane >> 2);
                bh[j][0] = BsH[cur][rB][c];
                bh[j][1] = BsH[cur][rB + 4][c];
                bl[j][0] = BsL[cur][rB][c];
                bl[j][1] = BsL[cur][rB + 4][c];
            }
            #pragma unroll
            for (int i = 0; i < 2; i++)
                #pragma unroll
                for (int j = 0; j < 4; j++) {
                    float* d = acc[i][jh * 4 + j];
                    MMA_BF16(d, ah[i], bh[j]);
                    MMA_BF16(d, al[i], bh[j]);
                    MMA_BF16(d, ah[i], bl[j]);
                }
        }
    }
    // epilogue
    #pragma unroll
    for (int i = 0; i < 2; i++) {
        int r0 = mBase + wm + i * 16 + (lane >> 2);
        #pragma unroll
        for (int j = 0; j < 8; j++) {
            int c = wn + j * 8 + (lane & 3) * 2;   // even column pair (c, c+1)
            #pragma unroll
            for (int half = 0; half < 2; half++) {
                int row = r0 + half * 8;
                if (row < M) {
                    float vx = acc[i][j][half * 2 + 0];
                    float vy = acc[i][j][half * 2 + 1];
                    if (PACK) {
                        vx = fmaxf(vx + bias[zC + c + 0], 0.f);
                        vy = fmaxf(vy + bias[zC + c + 1], 0.f);
                        uint32_t H, L;
                        packHL(vx, vy, H, L);
                        size_t wi = (size_t)row * 256 + ((zC + c) >> 1);
                        CH[wi] = H;
                        CL[wi] = L;
                    } else {
                        *(float2*)(C + (size_t)row * ldc + zC + c) = make_float2(vx, vy);
                    }
                }
            }
        }
    }
}

// ---------------- launch ----------------
extern "C" void kernel_launch(void* const* d_in, const int* in_sizes, int n_in,
                              void* d_out, int out_size) {
    const float* x   = (const float*)d_in[0];
    const int*   ei  = (const int*)d_in[1];      // int32
    const float* W1  = (const float*)d_in[2];
    const float* a1s = (const float*)d_in[3];
    const float* a1d = (const float*)d_in[4];
    const float* b1  = (const float*)d_in[5];
    const float* W2  = (const float*)d_in[6];
    const float* a2s = (const float*)d_in[7];
    const float* a2d = (const float*)d_in[8];
    const float* b2  = (const float*)d_in[9];
    const float* fcw = (const float*)d_in[10];
    const float* fcb = (const float*)d_in[11];
    float*       out = (float*)d_out;

    const int N = in_sizes[0] / 128;
    const int E = in_sizes[1] / 2;

    uint32_t *aggH, *aggL, *h1H, *h1L, *w1H, *w1L, *w2H, *w2L;
    float *h2pre;
    cudaGetSymbolAddress((void**)&aggH,  g_aggH);
    cudaGetSymbolAddress((void**)&aggL,  g_aggL);
    cudaGetSymbolAddress((void**)&h1H,   g_h1H);
    cudaGetSymbolAddress((void**)&h1L,   g_h1L);
    cudaGetSymbolAddress((void**)&w1H,   g_w1H);
    cudaGetSymbolAddress((void**)&w1L,   g_w1L);
    cudaGetSymbolAddress((void**)&w2H,   g_w2H);
    cudaGetSymbolAddress((void**)&w2L,   g_w2L);
    cudaGetSymbolAddress((void**)&h2pre, g_h2pre);

    const int* e_src = ei;
    const int* e_dst = ei + E;

    // prep (W pack + cnt init) + CSR by destination
    k_prep<<<(65536 + N + 255) / 256, 256>>>(W1, W2, N);
    k_hist<<<(E + 255) / 256, 256>>>(e_dst, E);
    k_scan<<<1, 1024>>>(N);
    k_scatter<<<(E + N + 255) / 256, 256>>>(e_src, e_dst, E, N);

    // ---- layer 1 (H=4, C=128): weights+aggregate raw x, then block-diagonal GEMM ----
    k_prep_ws<<<1, 512>>>(W1, a1s, a1d);
    k_scores1<<<(N * 32 + 255) / 256, 256>>>(x, N);
    k_edge1<<<(N * 32 + 255) / 256, 256>>>(x, N);
    {
        dim3 grid(1, (N + 127) / 128, 4);   // z = head
        mma_gemm<true><<<grid, 256>>>(N, 8, aggH, aggL, 256, 64,
                                      w1H, w1L, 512, 128,
                                      nullptr, h1H, h1L, 0, 128, b1);
    }

    // ---- layer 2 (H=1, C=128): project then weights+aggregate+FC ----
    {
        dim3 grid(1, (N + 127) / 128, 1);
        mma_gemm<false><<<grid, 256>>>(N, 32, h1H, h1L, 256, 0,
                                       w2H, w2L, 128, 0,
                                       h2pre, nullptr, nullptr, 128, 0, nullptr);
    }
    k_scores2<<<(N * 32 + 255) / 256, 256>>>(h2pre, a2s, a2d, N);
    k_edge2<<<(N * 32 + 255) / 256, 256>>>(b2, fcw, fcb, out, N);
}